// round 1
// baseline (speedup 1.0000x reference)
#include <cuda_runtime.h>

#define NN 20000

// ---------------- device scratch (no allocations allowed) ----------------
__device__ float g_z1 [NN * 64];
__device__ float g_hd1[NN * 64];
__device__ float g_zc [NN * 64];
__device__ float g_z2 [NN * 128];
__device__ float g_hd2[NN * 128];

// ---------------- helpers ----------------
__device__ __forceinline__ float warpSumAll(float v) {
#pragma unroll
    for (int o = 16; o > 0; o >>= 1) v += __shfl_xor_sync(0xffffffffu, v, o);
    return v;
}
__device__ __forceinline__ float warpMaxAll(float v) {
#pragma unroll
    for (int o = 16; o > 0; o >>= 1) v = fmaxf(v, __shfl_xor_sync(0xffffffffu, v, o));
    return v;
}
__device__ __forceinline__ float lrelu(float x) { return x > 0.f ? x : 0.01f * x; }

// elu with accurate expm1 behavior near 0 (cheap poly), MUFU exp otherwise
__device__ __forceinline__ float eluf(float x) {
    if (x > 0.f) return x;
    if (x > -0.25f)
        return x * (1.f + x * (0.5f + x * (0.16666667f + x * 0.041666667f)));
    return __expf(x) - 1.f;
}

union F2U { float2 f; unsigned long long u; };
// packed dual-fp32 FMA (Blackwell f32x2 pipe): c = a*b + c elementwise
__device__ __forceinline__ void fma2(float2& c, float2 a, float2 b) {
    F2U A, B, C; A.f = a; B.f = b; C.f = c;
    asm("fma.rn.f32x2 %0, %1, %2, %0;" : "+l"(C.u) : "l"(A.u), "l"(B.u));
    c = C.f;
}

// ---------------- fused dual GEMM: Z = A @ Wa^T, HD = A @ Wb^T ----------------
// A: [NN, KDIM], Wa/Wb: [H, KDIM], Z/HD: [NN, H]
// block = 256 threads; thread computes 8 nodes x 4 outdims with f32x2 dual-k accum
template <int KDIM, int H>
__global__ __launch_bounds__(256) void gemm2k(const float* __restrict__ A,
                                              const float* __restrict__ Wa,
                                              const float* __restrict__ Wb,
                                              float* __restrict__ Z,
                                              float* __restrict__ HD) {
    constexpr int OUT   = 2 * H;
    constexpr int OCR   = OUT / 4;      // outdim groups per thread-col
    constexpr int NG    = 256 / OCR;    // node groups
    constexpr int MTILE = NG * 8;       // nodes per block
    constexpr int KC    = 32;
    constexpr int NCH   = KDIM / KC;

    __shared__ __align__(16) float As[MTILE][KC];
    __shared__ __align__(16) float Ws[OUT][KC + 2];   // pad 2 (float2-aligned, reduces conflicts)

    const int t     = threadIdx.x;
    const int oc    = t % OCR;
    const int nr    = t / OCR;          // constant within a warp -> As broadcast
    const int node0 = blockIdx.x * MTILE;

    float2 acc[8][4];
#pragma unroll
    for (int i = 0; i < 8; i++)
#pragma unroll
        for (int j = 0; j < 4; j++) acc[i][j] = make_float2(0.f, 0.f);

    for (int ch = 0; ch < NCH; ch++) {
        const int kk = ch * KC;
        // stage A chunk
        for (int idx = t; idx < MTILE * KC; idx += 256) {
            int row = idx >> 5, k = idx & 31;
            int node = node0 + row;
            As[row][k] = (node < NN) ? A[node * KDIM + kk + k] : 0.f;
        }
        // stage W chunk (Wa rows then Wb rows)
        for (int idx = t; idx < OUT * KC; idx += 256) {
            int row = idx >> 5, k = idx & 31;
            Ws[row][k] = (row < H) ? Wa[row * KDIM + kk + k]
                                   : Wb[(row - H) * KDIM + kk + k];
        }
        __syncthreads();

#pragma unroll
        for (int k = 0; k < KC; k += 2) {
            float2 a[8], w[4];
#pragma unroll
            for (int i = 0; i < 8; i++)
                a[i] = *(const float2*)&As[nr * 8 + i][k];
#pragma unroll
            for (int j = 0; j < 4; j++)
                w[j] = *(const float2*)&Ws[oc + j * OCR][k];
#pragma unroll
            for (int i = 0; i < 8; i++)
#pragma unroll
                for (int j = 0; j < 4; j++) fma2(acc[i][j], a[i], w[j]);
        }
        __syncthreads();
    }

#pragma unroll
    for (int i = 0; i < 8; i++) {
        int node = node0 + nr * 8 + i;
        if (node >= NN) continue;
#pragma unroll
        for (int j = 0; j < 4; j++) {
            int od = oc + j * OCR;
            float v = acc[i][j].x + acc[i][j].y;
            if (od < H) Z[node * H + od] = v;
            else        HD[node * H + (od - H)] = v;
        }
    }
}

// ---------------- encoder aggregation: all 3 hops + hop-attention combine ----------------
// 64 nodes per block, warp per node (8 nodes each), window = 25 rows (deg of A^3)
__global__ __launch_bounds__(256) void enc_agg(const float* __restrict__ attE,
                                               const float* __restrict__ attC) {
    __shared__ __align__(16) float hdT[88][64];
    __shared__ float sT[88];
    __shared__ float sAe[64], sAc[64];

    const int t = threadIdx.x, w = t >> 5, lane = t & 31;
    const int nodeBase = blockIdx.x * 64;

    if (t < 64) { sAe[t] = attE[t]; sAc[t] = attC[t]; }

    // stage hd window (rows nodeBase-24 .. nodeBase+63, mod N)
    for (int r = w; r < 88; r += 8) {
        int g = nodeBase - 24 + r;
        if (g < 0) g += NN; else if (g >= NN) g -= NN;
        ((float2*)hdT[r])[lane] = ((const float2*)(g_hd1 + g * 64))[lane];
    }
    __syncthreads();

    // s[r] = hd[r] . att_enc
    for (int r = w; r < 88; r += 8) {
        float2 hv = ((float2*)hdT[r])[lane];
        float p = hv.x * sAe[2 * lane] + hv.y * sAe[2 * lane + 1];
        p = warpSumAll(p);
        if (lane == 0) sT[r] = p;
    }
    __syncthreads();

    const float ac0 = sAc[2 * lane], ac1 = sAc[2 * lane + 1];

    for (int i = 0; i < 8; i++) {
        const int node = nodeBase + w * 8 + i;
        if (node >= NN) return;               // uniform within warp
        const int li = 24 + w * 8 + i;
        const float s_i = sT[li];

        float el = -1e30f;
        if (lane < 25) el = lrelu(sT[li - lane] - s_i);
        const float m1 = warpMaxAll(lane < 9  ? el : -1e30f);
        const float m2 = warpMaxAll(lane < 17 ? el : -1e30f);
        const float m3 = warpMaxAll(el);
        const float ex1 = (lane < 9)  ? __expf(el - m1) : 0.f;
        const float ex2 = (lane < 17) ? __expf(el - m2) : 0.f;
        const float ex3 = (lane < 25) ? __expf(el - m3) : 0.f;
        const float r1 = 1.f / warpSumAll(ex1);
        const float r2 = 1.f / warpSumAll(ex2);
        const float r3 = 1.f / warpSumAll(ex3);

        float2 A1 = make_float2(0.f, 0.f), A2 = A1, A3 = A1;
#pragma unroll
        for (int tt = 0; tt < 25; tt++) {
            float2 hv = ((float2*)hdT[li - tt])[lane];
            float w3 = __shfl_sync(0xffffffffu, ex3, tt) * r3;
            A3.x = fmaf(w3, hv.x, A3.x); A3.y = fmaf(w3, hv.y, A3.y);
            if (tt < 17) {
                float w2 = __shfl_sync(0xffffffffu, ex2, tt) * r2;
                A2.x = fmaf(w2, hv.x, A2.x); A2.y = fmaf(w2, hv.y, A2.y);
            }
            if (tt < 9) {
                float w1 = __shfl_sync(0xffffffffu, ex1, tt) * r1;
                A1.x = fmaf(w1, hv.x, A1.x); A1.y = fmaf(w1, hv.y, A1.y);
            }
        }

        const float2 hvi = ((float2*)hdT[li])[lane];
        const float2 zv  = ((const float2*)(g_z1 + node * 64))[lane];
        float2 Z1, Z2, Z3;
        Z1.x = eluf(zv.x + A1.x - hvi.x); Z1.y = eluf(zv.y + A1.y - hvi.y);
        Z2.x = eluf(zv.x + A2.x - hvi.x); Z2.y = eluf(zv.y + A2.y - hvi.y);
        Z3.x = eluf(zv.x + A3.x - hvi.x); Z3.y = eluf(zv.y + A3.y - hvi.y);

        // hop-attention combine
        const float c1 = warpSumAll(Z1.x * ac0 + Z1.y * ac1);
        const float c2 = warpSumAll(Z2.x * ac0 + Z2.y * ac1);
        const float c3 = warpSumAll(Z3.x * ac0 + Z3.y * ac1);
        const float l1 = lrelu(c1), l2 = lrelu(c2), l3 = lrelu(c3);
        const float mx = fmaxf(l1, fmaxf(l2, l3));
        const float e1 = __expf(l1 - mx), e2 = __expf(l2 - mx), e3 = __expf(l3 - mx);
        const float rd = 1.f / (e1 + e2 + e3);
        const float b1 = e1 * rd, b2 = e2 * rd, b3 = e3 * rd;

        float2 o;
        o.x = b1 * Z1.x + b2 * Z2.x + b3 * Z3.x;
        o.y = b1 * Z1.y + b2 * Z2.y + b3 * Z3.y;
        ((float2*)(g_zc + node * 64))[lane] = o;
    }
}

// ---------------- decoder aggregation (deg 25, 128 dims, no elu) ----------------
__global__ __launch_bounds__(256) void dec_agg(const float* __restrict__ attD,
                                               float* __restrict__ out) {
    __shared__ __align__(16) float hdT[88][128];
    __shared__ float sT[88];
    __shared__ __align__(16) float sA[128];

    const int t = threadIdx.x, w = t >> 5, lane = t & 31;
    const int nodeBase = blockIdx.x * 64;

    if (t < 128) sA[t] = attD[t];

    for (int r = w; r < 88; r += 8) {
        int g = nodeBase - 24 + r;
        if (g < 0) g += NN; else if (g >= NN) g -= NN;
        ((float4*)hdT[r])[lane] = ((const float4*)(g_hd2 + g * 128))[lane];
    }
    __syncthreads();

    const float4 av = ((const float4*)sA)[lane];
    for (int r = w; r < 88; r += 8) {
        float4 hv = ((float4*)hdT[r])[lane];
        float p = hv.x * av.x + hv.y * av.y + hv.z * av.z + hv.w * av.w;
        p = warpSumAll(p);
        if (lane == 0) sT[r] = p;
    }
    __syncthreads();

    for (int i = 0; i < 8; i++) {
        const int node = nodeBase + w * 8 + i;
        if (node >= NN) return;
        const int li = 24 + w * 8 + i;
        const float s_i = sT[li];

        float el = (lane < 25) ? lrelu(sT[li - lane] - s_i) : -1e30f;
        const float m = warpMaxAll(el);
        const float ex = (lane < 25) ? __expf(el - m) : 0.f;
        const float rd = 1.f / warpSumAll(ex);

        float4 A = make_float4(0.f, 0.f, 0.f, 0.f);
#pragma unroll
        for (int tt = 0; tt < 25; tt++) {
            float4 hv = ((float4*)hdT[li - tt])[lane];
            float wg = __shfl_sync(0xffffffffu, ex, tt) * rd;
            A.x = fmaf(wg, hv.x, A.x); A.y = fmaf(wg, hv.y, A.y);
            A.z = fmaf(wg, hv.z, A.z); A.w = fmaf(wg, hv.w, A.w);
        }

        const float4 hvi = ((float4*)hdT[li])[lane];
        const float4 zv  = ((const float4*)(g_z2 + node * 128))[lane];
        float4 o;
        o.x = zv.x + A.x - hvi.x; o.y = zv.y + A.y - hvi.y;
        o.z = zv.z + A.z - hvi.z; o.w = zv.w + A.w - hvi.w;
        ((float4*)(out + node * 128))[lane] = o;
    }
}

// ---------------- launch ----------------
extern "C" void kernel_launch(void* const* d_in, const int* in_sizes, int n_in,
                              void* d_out, int out_size) {
    const float* h        = (const float*)d_in[0];
    const float* fc_enc   = (const float*)d_in[1];
    const float* diff_enc = (const float*)d_in[2];
    const float* att_enc  = (const float*)d_in[3];
    const float* fc_dec   = (const float*)d_in[4];
    const float* diff_dec = (const float*)d_in[5];
    const float* att_dec  = (const float*)d_in[6];
    const float* att_comb = (const float*)d_in[7];
    float* out = (float*)d_out;

    void *p;
    cudaGetSymbolAddress(&p, g_z1);  float* z1 = (float*)p;
    cudaGetSymbolAddress(&p, g_hd1); float* hd1 = (float*)p;
    cudaGetSymbolAddress(&p, g_zc);  float* zc = (float*)p;
    cudaGetSymbolAddress(&p, g_z2);  float* z2 = (float*)p;
    cudaGetSymbolAddress(&p, g_hd2); float* hd2 = (float*)p;

    const int encBlocks  = (NN + 63) / 64;   // 313
    const int decGBlocks = (NN + 31) / 32;   // 625

    // encoder: shared z/hd/s across all 3 hops (same weights!)
    gemm2k<128, 64><<<encBlocks, 256>>>(h, fc_enc, diff_enc, z1, hd1);
    // 3-hop windowed softmax-aggregation + hop-attention combine, fused
    enc_agg<<<encBlocks, 256>>>(att_enc, att_comb);
    // decoder projections
    gemm2k<64, 128><<<decGBlocks, 256>>>(zc, fc_dec, diff_dec, z2, hd2);
    // decoder aggregation on A^3 graph
    dec_agg<<<encBlocks, 256>>>(att_dec, out);
}

// round 2
// speedup vs baseline: 1.1086x; 1.1086x over previous
#include <cuda_runtime.h>

#define NN 20000

// ---------------- device scratch ----------------
__device__ float g_z1 [NN * 64];
__device__ float g_hd1[NN * 64];
__device__ float g_zc [NN * 64];
__device__ float g_u  [NN * 64];

// ---------------- helpers ----------------
__device__ __forceinline__ float warpSumAll(float v) {
#pragma unroll
    for (int o = 16; o > 0; o >>= 1) v += __shfl_xor_sync(0xffffffffu, v, o);
    return v;
}
__device__ __forceinline__ float warpMaxAll(float v) {
#pragma unroll
    for (int o = 16; o > 0; o >>= 1) v = fmaxf(v, __shfl_xor_sync(0xffffffffu, v, o));
    return v;
}
__device__ __forceinline__ float lrelu(float x) { return x > 0.f ? x : 0.01f * x; }

__device__ __forceinline__ float eluf(float x) {
    if (x > 0.f) return x;
    if (x > -0.25f)
        return x * (1.f + x * (0.5f + x * (0.16666667f + x * 0.041666667f)));
    return __expf(x) - 1.f;
}

union F2U { float2 f; unsigned long long u; };
__device__ __forceinline__ void fma2(float2& c, float2 a, float2 b) {
    F2U A, B, C; A.f = a; B.f = b; C.f = c;
    asm("fma.rn.f32x2 %0, %1, %2, %0;" : "+l"(C.u) : "l"(A.u), "l"(B.u));
    c = C.f;
}

// ---------------- fused dual GEMM: Z = A @ Wa^T, HD = A @ Wb^T ----------------
template <int KDIM, int H>
__global__ __launch_bounds__(256) void gemm2k(const float* __restrict__ A,
                                              const float* __restrict__ Wa,
                                              const float* __restrict__ Wb,
                                              float* __restrict__ Z,
                                              float* __restrict__ HD) {
    constexpr int OUT   = 2 * H;
    constexpr int OCR   = OUT / 4;
    constexpr int NG    = 256 / OCR;
    constexpr int MTILE = NG * 8;
    constexpr int KC    = 32;
    constexpr int NCH   = KDIM / KC;

    __shared__ __align__(16) float As[MTILE][KC];
    __shared__ __align__(16) float Ws[OUT][KC + 2];

    const int t     = threadIdx.x;
    const int oc    = t % OCR;
    const int nr    = t / OCR;
    const int node0 = blockIdx.x * MTILE;

    float2 acc[8][4];
#pragma unroll
    for (int i = 0; i < 8; i++)
#pragma unroll
        for (int j = 0; j < 4; j++) acc[i][j] = make_float2(0.f, 0.f);

    for (int ch = 0; ch < NCH; ch++) {
        const int kk = ch * KC;
        for (int idx = t; idx < MTILE * KC; idx += 256) {
            int row = idx >> 5, k = idx & 31;
            int node = node0 + row;
            As[row][k] = (node < NN) ? A[node * KDIM + kk + k] : 0.f;
        }
        for (int idx = t; idx < OUT * KC; idx += 256) {
            int row = idx >> 5, k = idx & 31;
            Ws[row][k] = (row < H) ? Wa[row * KDIM + kk + k]
                                   : Wb[(row - H) * KDIM + kk + k];
        }
        __syncthreads();

#pragma unroll
        for (int k = 0; k < KC; k += 2) {
            float2 a[8], w[4];
#pragma unroll
            for (int i = 0; i < 8; i++)
                a[i] = *(const float2*)&As[nr * 8 + i][k];
#pragma unroll
            for (int j = 0; j < 4; j++)
                w[j] = *(const float2*)&Ws[oc + j * OCR][k];
#pragma unroll
            for (int i = 0; i < 8; i++)
#pragma unroll
                for (int j = 0; j < 4; j++) fma2(acc[i][j], a[i], w[j]);
        }
        __syncthreads();
    }

#pragma unroll
    for (int i = 0; i < 8; i++) {
        int node = node0 + nr * 8 + i;
        if (node >= NN) continue;
#pragma unroll
        for (int j = 0; j < 4; j++) {
            int od = oc + j * OCR;
            float v = acc[i][j].x + acc[i][j].y;
            if (od < H) Z[node * H + od] = v;
            else        HD[node * H + (od - H)] = v;
        }
    }
}

// ---------------- decoder-combine GEMM: out = zc@fcD^T + u@diffD^T ----------------
__global__ __launch_bounds__(256) void gemm_dec(const float* __restrict__ fcD,
                                                const float* __restrict__ diffD,
                                                float* __restrict__ out) {
    constexpr int KC = 32;
    __shared__ __align__(16) float As[64][KC];
    __shared__ __align__(16) float Ws[128][KC + 2];

    const int t     = threadIdx.x;
    const int oc    = t & 31;
    const int nr    = t >> 5;
    const int node0 = blockIdx.x * 64;

    float2 acc[8][4];
#pragma unroll
    for (int i = 0; i < 8; i++)
#pragma unroll
        for (int j = 0; j < 4; j++) acc[i][j] = make_float2(0.f, 0.f);

#pragma unroll
    for (int part = 0; part < 2; part++) {
        const float* Asrc = part ? g_u : g_zc;
        const float* Wsrc = part ? diffD : fcD;
#pragma unroll
        for (int ch = 0; ch < 2; ch++) {
            const int kk = ch * KC;
            for (int idx = t; idx < 64 * KC; idx += 256) {
                int row = idx >> 5, k = idx & 31;
                int node = node0 + row;
                As[row][k] = (node < NN) ? Asrc[node * 64 + kk + k] : 0.f;
            }
            for (int idx = t; idx < 128 * KC; idx += 256) {
                int row = idx >> 5, k = idx & 31;
                Ws[row][k] = Wsrc[row * 64 + kk + k];
            }
            __syncthreads();

#pragma unroll
            for (int k = 0; k < KC; k += 2) {
                float2 a[8], w[4];
#pragma unroll
                for (int i = 0; i < 8; i++)
                    a[i] = *(const float2*)&As[nr * 8 + i][k];
#pragma unroll
                for (int j = 0; j < 4; j++)
                    w[j] = *(const float2*)&Ws[oc + j * 32][k];
#pragma unroll
                for (int i = 0; i < 8; i++)
#pragma unroll
                    for (int j = 0; j < 4; j++) fma2(acc[i][j], a[i], w[j]);
            }
            __syncthreads();
        }
    }

#pragma unroll
    for (int i = 0; i < 8; i++) {
        int node = node0 + nr * 8 + i;
        if (node >= NN) continue;
#pragma unroll
        for (int j = 0; j < 4; j++) {
            int od = oc + j * 32;
            out[node * 128 + od] = acc[i][j].x + acc[i][j].y;
        }
    }
}

// ---------------- encoder aggregation: 3 hops + hop-attention combine ----------------
// 32 nodes/block (grid 625), warp handles 4 nodes concurrently
__global__ __launch_bounds__(256) void enc_agg(const float* __restrict__ attE,
                                               const float* __restrict__ attC) {
    __shared__ __align__(16) float hdT[56][66];
    __shared__ float sT[56];
    __shared__ __align__(16) float wS[3][25][36];
    __shared__ float sAe[64], sAc[64];

    const int t = threadIdx.x, w = t >> 5, lane = t & 31;
    const int nodeBase = blockIdx.x * 32;
    const int nl0 = w * 4;

    if (t < 64) { sAe[t] = attE[t]; sAc[t] = attC[t]; }

    // stage hd window: rows nodeBase-24 .. nodeBase+31
    for (int r = w; r < 56; r += 8) {
        int g = nodeBase - 24 + r;
        if (g < 0) g += NN;
        ((float2*)hdT[r])[lane] = ((const float2*)(g_hd1 + g * 64))[lane];
    }
    __syncthreads();

    // s[r] = hd[r] . att_enc
    for (int r = w; r < 56; r += 8) {
        float2 hv = ((float2*)hdT[r])[lane];
        float p = warpSumAll(hv.x * sAe[2 * lane] + hv.y * sAe[2 * lane + 1]);
        if (lane == 0) sT[r] = p;
    }
    __syncthreads();

    // softmax weights for this warp's 4 nodes (all 3 hops), into smem
#pragma unroll
    for (int j = 0; j < 4; j++) {
        const int li = 24 + nl0 + j;
        const float s_i = sT[li];
        float el = (lane < 25) ? lrelu(sT[li - lane] - s_i) : -1e30f;
        const float m1 = warpMaxAll(lane < 9  ? el : -1e30f);
        const float m2 = warpMaxAll(lane < 17 ? el : -1e30f);
        const float m3 = warpMaxAll(el);
        const float ex1 = (lane < 9)  ? __expf(el - m1) : 0.f;
        const float ex2 = (lane < 17) ? __expf(el - m2) : 0.f;
        const float ex3 = (lane < 25) ? __expf(el - m3) : 0.f;
        const float r1 = 1.f / warpSumAll(ex1);
        const float r2 = 1.f / warpSumAll(ex2);
        const float r3 = 1.f / warpSumAll(ex3);
        if (lane < 25) {
            wS[0][lane][nl0 + j] = ex1 * r1;
            wS[1][lane][nl0 + j] = ex2 * r2;
            wS[2][lane][nl0 + j] = ex3 * r3;
        }
    }
    __syncwarp();

    // tap loop: 4 nodes x 3 hops accumulated concurrently
    float2 A[4][3];
#pragma unroll
    for (int j = 0; j < 4; j++)
#pragma unroll
        for (int hh = 0; hh < 3; hh++) A[j][hh] = make_float2(0.f, 0.f);

#pragma unroll
    for (int tt = 0; tt < 25; tt++) {
        const float4 w3 = *(const float4*)&wS[2][tt][nl0];
        float4 w2, w1;
        if (tt < 17) w2 = *(const float4*)&wS[1][tt][nl0];
        if (tt < 9)  w1 = *(const float4*)&wS[0][tt][nl0];
#pragma unroll
        for (int j = 0; j < 4; j++) {
            const float2 hv = ((float2*)hdT[24 + nl0 + j - tt])[lane];
            const float g3 = ((const float*)&w3)[j];
            A[j][2].x = fmaf(g3, hv.x, A[j][2].x);
            A[j][2].y = fmaf(g3, hv.y, A[j][2].y);
            if (tt < 17) {
                const float g2 = ((const float*)&w2)[j];
                A[j][1].x = fmaf(g2, hv.x, A[j][1].x);
                A[j][1].y = fmaf(g2, hv.y, A[j][1].y);
            }
            if (tt < 9) {
                const float g1 = ((const float*)&w1)[j];
                A[j][0].x = fmaf(g1, hv.x, A[j][0].x);
                A[j][0].y = fmaf(g1, hv.y, A[j][0].y);
            }
        }
    }

    const float ac0 = sAc[2 * lane], ac1 = sAc[2 * lane + 1];
#pragma unroll
    for (int j = 0; j < 4; j++) {
        const int li = 24 + nl0 + j;
        const int node = nodeBase + nl0 + j;
        const float2 hvi = ((float2*)hdT[li])[lane];
        const float2 zv  = ((const float2*)(g_z1 + node * 64))[lane];
        float2 Z1, Z2, Z3;
        Z1.x = eluf(zv.x + A[j][0].x - hvi.x); Z1.y = eluf(zv.y + A[j][0].y - hvi.y);
        Z2.x = eluf(zv.x + A[j][1].x - hvi.x); Z2.y = eluf(zv.y + A[j][1].y - hvi.y);
        Z3.x = eluf(zv.x + A[j][2].x - hvi.x); Z3.y = eluf(zv.y + A[j][2].y - hvi.y);

        const float c1 = warpSumAll(Z1.x * ac0 + Z1.y * ac1);
        const float c2 = warpSumAll(Z2.x * ac0 + Z2.y * ac1);
        const float c3 = warpSumAll(Z3.x * ac0 + Z3.y * ac1);
        const float l1 = lrelu(c1), l2 = lrelu(c2), l3 = lrelu(c3);
        const float mx = fmaxf(l1, fmaxf(l2, l3));
        const float e1 = __expf(l1 - mx), e2 = __expf(l2 - mx), e3 = __expf(l3 - mx);
        const float rd = 1.f / (e1 + e2 + e3);

        float2 o;
        o.x = (e1 * Z1.x + e2 * Z2.x + e3 * Z3.x) * rd;
        o.y = (e1 * Z1.y + e2 * Z2.y + e3 * Z3.y) * rd;
        ((float2*)(g_zc + node * 64))[lane] = o;
    }
}

// ---------------- decoder aggregation in 64-dim latent space ----------------
// s_i = zc[i].v  (v = diffD^T attD);  u[i] = sum_t w_t zc[i-t] - zc[i]
__global__ __launch_bounds__(256) void dec_agg(const float* __restrict__ diffD,
                                               const float* __restrict__ attD) {
    __shared__ __align__(16) float zT[56][66];
    __shared__ float sT[56];
    __shared__ __align__(16) float wS[25][36];
    __shared__ float sv[64];

    const int t = threadIdx.x, w = t >> 5, lane = t & 31;
    const int nodeBase = blockIdx.x * 32;
    const int nl0 = w * 4;

    // v[k] = sum_od diffD[od][k] * attD[od]
    if (t < 64) {
        float a = 0.f;
#pragma unroll 4
        for (int od = 0; od < 128; od++) a = fmaf(diffD[od * 64 + t], attD[od], a);
        sv[t] = a;
    }

    for (int r = w; r < 56; r += 8) {
        int g = nodeBase - 24 + r;
        if (g < 0) g += NN;
        ((float2*)zT[r])[lane] = ((const float2*)(g_zc + g * 64))[lane];
    }
    __syncthreads();

    for (int r = w; r < 56; r += 8) {
        float2 zv = ((float2*)zT[r])[lane];
        float p = warpSumAll(zv.x * sv[2 * lane] + zv.y * sv[2 * lane + 1]);
        if (lane == 0) sT[r] = p;
    }
    __syncthreads();

#pragma unroll
    for (int j = 0; j < 4; j++) {
        const int li = 24 + nl0 + j;
        const float s_i = sT[li];
        float el = (lane < 25) ? lrelu(sT[li - lane] - s_i) : -1e30f;
        const float m = warpMaxAll(el);
        const float ex = (lane < 25) ? __expf(el - m) : 0.f;
        const float rd = 1.f / warpSumAll(ex);
        if (lane < 25) wS[lane][nl0 + j] = ex * rd;
    }
    __syncwarp();

    float2 A[4];
#pragma unroll
    for (int j = 0; j < 4; j++) A[j] = make_float2(0.f, 0.f);

#pragma unroll
    for (int tt = 0; tt < 25; tt++) {
        const float4 wv = *(const float4*)&wS[tt][nl0];
#pragma unroll
        for (int j = 0; j < 4; j++) {
            const float2 zv = ((float2*)zT[24 + nl0 + j - tt])[lane];
            const float g = ((const float*)&wv)[j];
            A[j].x = fmaf(g, zv.x, A[j].x);
            A[j].y = fmaf(g, zv.y, A[j].y);
        }
    }

#pragma unroll
    for (int j = 0; j < 4; j++) {
        const int li = 24 + nl0 + j;
        const int node = nodeBase + nl0 + j;
        const float2 zvi = ((float2*)zT[li])[lane];
        float2 o;
        o.x = A[j].x - zvi.x;
        o.y = A[j].y - zvi.y;
        ((float2*)(g_u + node * 64))[lane] = o;
    }
}

// ---------------- launch ----------------
extern "C" void kernel_launch(void* const* d_in, const int* in_sizes, int n_in,
                              void* d_out, int out_size) {
    const float* h        = (const float*)d_in[0];
    const float* fc_enc   = (const float*)d_in[1];
    const float* diff_enc = (const float*)d_in[2];
    const float* att_enc  = (const float*)d_in[3];
    const float* fc_dec   = (const float*)d_in[4];
    const float* diff_dec = (const float*)d_in[5];
    const float* att_dec  = (const float*)d_in[6];
    const float* att_comb = (const float*)d_in[7];
    float* out = (float*)d_out;

    void *p;
    cudaGetSymbolAddress(&p, g_z1);  float* z1  = (float*)p;
    cudaGetSymbolAddress(&p, g_hd1); float* hd1 = (float*)p;

    gemm2k<128, 64><<<(NN + 63) / 64, 256>>>(h, fc_enc, diff_enc, z1, hd1);
    enc_agg<<<NN / 32, 256>>>(att_enc, att_comb);
    dec_agg<<<NN / 32, 256>>>(diff_dec, att_dec);
    gemm_dec<<<(NN + 63) / 64, 256>>>(fc_dec, diff_dec, out);
}

// round 3
// speedup vs baseline: 1.2177x; 1.0984x over previous
#include <cuda_runtime.h>

#define NN 20000

// ---------------- device scratch ----------------
__device__ float g_z1 [NN * 64];
__device__ float g_hd1[NN * 64];
__device__ float g_zc [NN * 64];
__device__ float g_u  [NN * 64];

// ---------------- helpers ----------------
__device__ __forceinline__ float warpSumAll(float v) {
#pragma unroll
    for (int o = 16; o > 0; o >>= 1) v += __shfl_xor_sync(0xffffffffu, v, o);
    return v;
}
__device__ __forceinline__ float warpMaxAll(float v) {
#pragma unroll
    for (int o = 16; o > 0; o >>= 1) v = fmaxf(v, __shfl_xor_sync(0xffffffffu, v, o));
    return v;
}
__device__ __forceinline__ float lrelu(float x) { return x > 0.f ? x : 0.01f * x; }

__device__ __forceinline__ float eluf(float x) {
    if (x > 0.f) return x;
    if (x > -0.25f)
        return x * (1.f + x * (0.5f + x * (0.16666667f + x * 0.041666667f)));
    return __expf(x) - 1.f;
}

union F2U { float2 f; unsigned long long u; };
// c += (a,a) * b   elementwise, packed dual-fp32 FMA
__device__ __forceinline__ void fma2s(float2& c, float a, float2 b) {
    F2U A, B, C; A.f = make_float2(a, a); B.f = b; C.f = c;
    asm("fma.rn.f32x2 %0, %1, %2, %0;" : "+l"(C.u) : "l"(A.u), "l"(B.u));
    c = C.f;
}

// =====================================================================
// GEMM design (both): block=256 (8 warps), 64 nodes/block, warp -> 8 nodes.
// Lane l owns output dims {2l, 2l+1, 2l+64, 2l+65} (dual-output f32x2).
// W staged k-major + lane-interleaved: Ws[k][4l+sub] so one LDS.128 per k
// gives all 4 weights. A reads are warp-broadcast. acc[8][2] float2 = 32 regs.
// =====================================================================

// ---------------- encoder GEMM: Z = h@fcE^T, HD = h@dfE^T ----------------
__global__ __launch_bounds__(256, 3) void gemm_enc(const float* __restrict__ A,
                                                   const float* __restrict__ fcE,
                                                   const float* __restrict__ dfE,
                                                   float* __restrict__ Z,
                                                   float* __restrict__ HD) {
    __shared__ __align__(16) float As[64][32];
    __shared__ __align__(16) float Ws[32][132];   // 4*l+sub, pad 4

    const int t = threadIdx.x, lane = t & 31, w = t >> 5;
    const int node0 = blockIdx.x * 64;

    float2 acc[8][2];
#pragma unroll
    for (int i = 0; i < 8; i++) { acc[i][0] = make_float2(0.f, 0.f); acc[i][1] = make_float2(0.f, 0.f); }

    for (int ch = 0; ch < 4; ch++) {
        const int kk = ch * 32;
        for (int idx = t; idx < 64 * 32; idx += 256) {
            int row = idx >> 5, k = idx & 31;
            int node = node0 + row;
            As[row][k] = (node < NN) ? A[node * 128 + kk + k] : 0.f;
        }
        for (int idx = t; idx < 128 * 32; idx += 256) {
            int od = idx >> 5, k = idx & 31;
            float v = (od < 64) ? fcE[od * 128 + kk + k] : dfE[(od - 64) * 128 + kk + k];
            int l2  = (od & 63) >> 1;
            int sub = ((od >> 6) << 1) | (od & 1);
            Ws[k][4 * l2 + sub] = v;
        }
        __syncthreads();

#pragma unroll
        for (int k = 0; k < 32; k += 2) {
            const float4 wv0 = *(const float4*)&Ws[k][4 * lane];
            const float4 wv1 = *(const float4*)&Ws[k + 1][4 * lane];
            const float2 p00 = make_float2(wv0.x, wv0.y), p01 = make_float2(wv0.z, wv0.w);
            const float2 p10 = make_float2(wv1.x, wv1.y), p11 = make_float2(wv1.z, wv1.w);
#pragma unroll
            for (int i = 0; i < 8; i++) {
                const float2 a2 = *(const float2*)&As[w * 8 + i][k];
                fma2s(acc[i][0], a2.x, p00);
                fma2s(acc[i][1], a2.x, p01);
                fma2s(acc[i][0], a2.y, p10);
                fma2s(acc[i][1], a2.y, p11);
            }
        }
        __syncthreads();
    }

#pragma unroll
    for (int i = 0; i < 8; i++) {
        int node = node0 + w * 8 + i;
        if (node < NN) {
            ((float2*)(Z  + node * 64))[lane] = acc[i][0];
            ((float2*)(HD + node * 64))[lane] = acc[i][1];
        }
    }
}

// ---------------- decoder GEMM: out = zc@fcD^T + u@diffD^T ----------------
__global__ __launch_bounds__(256, 3) void gemm_dec(const float* __restrict__ fcD,
                                                   const float* __restrict__ diffD,
                                                   float* __restrict__ out) {
    __shared__ __align__(16) float As[64][32];
    __shared__ __align__(16) float Ws[32][132];

    const int t = threadIdx.x, lane = t & 31, w = t >> 5;
    const int node0 = blockIdx.x * 64;

    float2 acc[8][2];
#pragma unroll
    for (int i = 0; i < 8; i++) { acc[i][0] = make_float2(0.f, 0.f); acc[i][1] = make_float2(0.f, 0.f); }

    for (int ch = 0; ch < 4; ch++) {
        const float* Asrc = (ch < 2) ? g_zc : g_u;
        const float* Wsrc = (ch < 2) ? fcD : diffD;
        const int kk = (ch & 1) * 32;
        for (int idx = t; idx < 64 * 32; idx += 256) {
            int row = idx >> 5, k = idx & 31;
            int node = node0 + row;
            As[row][k] = (node < NN) ? Asrc[node * 64 + kk + k] : 0.f;
        }
        for (int idx = t; idx < 128 * 32; idx += 256) {
            int od = idx >> 5, k = idx & 31;
            float v = Wsrc[od * 64 + kk + k];
            int l2  = (od & 63) >> 1;
            int sub = ((od >> 6) << 1) | (od & 1);
            Ws[k][4 * l2 + sub] = v;
        }
        __syncthreads();

#pragma unroll
        for (int k = 0; k < 32; k += 2) {
            const float4 wv0 = *(const float4*)&Ws[k][4 * lane];
            const float4 wv1 = *(const float4*)&Ws[k + 1][4 * lane];
            const float2 p00 = make_float2(wv0.x, wv0.y), p01 = make_float2(wv0.z, wv0.w);
            const float2 p10 = make_float2(wv1.x, wv1.y), p11 = make_float2(wv1.z, wv1.w);
#pragma unroll
            for (int i = 0; i < 8; i++) {
                const float2 a2 = *(const float2*)&As[w * 8 + i][k];
                fma2s(acc[i][0], a2.x, p00);
                fma2s(acc[i][1], a2.x, p01);
                fma2s(acc[i][0], a2.y, p10);
                fma2s(acc[i][1], a2.y, p11);
            }
        }
        __syncthreads();
    }

#pragma unroll
    for (int i = 0; i < 8; i++) {
        int node = node0 + w * 8 + i;
        if (node < NN) {
            ((float2*)(out + node * 128))[lane]      = acc[i][0];
            ((float2*)(out + node * 128 + 64))[lane] = acc[i][1];
        }
    }
}

// ---------------- encoder aggregation: 3 hops + hop-attention combine ----------------
__global__ __launch_bounds__(256) void enc_agg(const float* __restrict__ attE,
                                               const float* __restrict__ attC) {
    __shared__ __align__(16) float hdT[56][66];
    __shared__ float sT[56];
    __shared__ __align__(16) float wS[3][25][36];
    __shared__ float sAe[64], sAc[64];

    const int t = threadIdx.x, w = t >> 5, lane = t & 31;
    const int nodeBase = blockIdx.x * 32;
    const int nl0 = w * 4;

    if (t < 64) { sAe[t] = attE[t]; sAc[t] = attC[t]; }

    for (int r = w; r < 56; r += 8) {
        int g = nodeBase - 24 + r;
        if (g < 0) g += NN;
        ((float2*)hdT[r])[lane] = ((const float2*)(g_hd1 + g * 64))[lane];
    }
    __syncthreads();

    for (int r = w; r < 56; r += 8) {
        float2 hv = ((float2*)hdT[r])[lane];
        float p = warpSumAll(hv.x * sAe[2 * lane] + hv.y * sAe[2 * lane + 1]);
        if (lane == 0) sT[r] = p;
    }
    __syncthreads();

#pragma unroll
    for (int j = 0; j < 4; j++) {
        const int li = 24 + nl0 + j;
        const float s_i = sT[li];
        float el = (lane < 25) ? lrelu(sT[li - lane] - s_i) : -1e30f;
        const float m1 = warpMaxAll(lane < 9  ? el : -1e30f);
        const float m2 = warpMaxAll(lane < 17 ? el : -1e30f);
        const float m3 = warpMaxAll(el);
        const float ex1 = (lane < 9)  ? __expf(el - m1) : 0.f;
        const float ex2 = (lane < 17) ? __expf(el - m2) : 0.f;
        const float ex3 = (lane < 25) ? __expf(el - m3) : 0.f;
        const float r1 = 1.f / warpSumAll(ex1);
        const float r2 = 1.f / warpSumAll(ex2);
        const float r3 = 1.f / warpSumAll(ex3);
        if (lane < 25) {
            wS[0][lane][nl0 + j] = ex1 * r1;
            wS[1][lane][nl0 + j] = ex2 * r2;
            wS[2][lane][nl0 + j] = ex3 * r3;
        }
    }
    __syncwarp();

    float2 A[4][3];
#pragma unroll
    for (int j = 0; j < 4; j++)
#pragma unroll
        for (int hh = 0; hh < 3; hh++) A[j][hh] = make_float2(0.f, 0.f);

#pragma unroll
    for (int tt = 0; tt < 25; tt++) {
        const float4 w3 = *(const float4*)&wS[2][tt][nl0];
        float4 w2, w1;
        if (tt < 17) w2 = *(const float4*)&wS[1][tt][nl0];
        if (tt < 9)  w1 = *(const float4*)&wS[0][tt][nl0];
#pragma unroll
        for (int j = 0; j < 4; j++) {
            const float2 hv = ((float2*)hdT[24 + nl0 + j - tt])[lane];
            const float g3 = ((const float*)&w3)[j];
            A[j][2].x = fmaf(g3, hv.x, A[j][2].x);
            A[j][2].y = fmaf(g3, hv.y, A[j][2].y);
            if (tt < 17) {
                const float g2 = ((const float*)&w2)[j];
                A[j][1].x = fmaf(g2, hv.x, A[j][1].x);
                A[j][1].y = fmaf(g2, hv.y, A[j][1].y);
            }
            if (tt < 9) {
                const float g1 = ((const float*)&w1)[j];
                A[j][0].x = fmaf(g1, hv.x, A[j][0].x);
                A[j][0].y = fmaf(g1, hv.y, A[j][0].y);
            }
        }
    }

    const float ac0 = sAc[2 * lane], ac1 = sAc[2 * lane + 1];
#pragma unroll
    for (int j = 0; j < 4; j++) {
        const int li = 24 + nl0 + j;
        const int node = nodeBase + nl0 + j;
        const float2 hvi = ((float2*)hdT[li])[lane];
        const float2 zv  = ((const float2*)(g_z1 + node * 64))[lane];
        float2 Z1, Z2, Z3;
        Z1.x = eluf(zv.x + A[j][0].x - hvi.x); Z1.y = eluf(zv.y + A[j][0].y - hvi.y);
        Z2.x = eluf(zv.x + A[j][1].x - hvi.x); Z2.y = eluf(zv.y + A[j][1].y - hvi.y);
        Z3.x = eluf(zv.x + A[j][2].x - hvi.x); Z3.y = eluf(zv.y + A[j][2].y - hvi.y);

        const float c1 = warpSumAll(Z1.x * ac0 + Z1.y * ac1);
        const float c2 = warpSumAll(Z2.x * ac0 + Z2.y * ac1);
        const float c3 = warpSumAll(Z3.x * ac0 + Z3.y * ac1);
        const float l1 = lrelu(c1), l2 = lrelu(c2), l3 = lrelu(c3);
        const float mx = fmaxf(l1, fmaxf(l2, l3));
        const float e1 = __expf(l1 - mx), e2 = __expf(l2 - mx), e3 = __expf(l3 - mx);
        const float rd = 1.f / (e1 + e2 + e3);

        float2 o;
        o.x = (e1 * Z1.x + e2 * Z2.x + e3 * Z3.x) * rd;
        o.y = (e1 * Z1.y + e2 * Z2.y + e3 * Z3.y) * rd;
        ((float2*)(g_zc + node * 64))[lane] = o;
    }
}

// ---------------- decoder aggregation in 64-dim latent ----------------
__global__ __launch_bounds__(256) void dec_agg(const float* __restrict__ diffD,
                                               const float* __restrict__ attD) {
    __shared__ __align__(16) float zT[56][66];
    __shared__ float sT[56];
    __shared__ __align__(16) float wS[25][36];
    __shared__ float sv[64];

    const int t = threadIdx.x, w = t >> 5, lane = t & 31;
    const int nodeBase = blockIdx.x * 32;
    const int nl0 = w * 4;

    if (t < 64) {
        float a = 0.f;
#pragma unroll 4
        for (int od = 0; od < 128; od++) a = fmaf(diffD[od * 64 + t], attD[od], a);
        sv[t] = a;
    }

    for (int r = w; r < 56; r += 8) {
        int g = nodeBase - 24 + r;
        if (g < 0) g += NN;
        ((float2*)zT[r])[lane] = ((const float2*)(g_zc + g * 64))[lane];
    }
    __syncthreads();

    for (int r = w; r < 56; r += 8) {
        float2 zv = ((float2*)zT[r])[lane];
        float p = warpSumAll(zv.x * sv[2 * lane] + zv.y * sv[2 * lane + 1]);
        if (lane == 0) sT[r] = p;
    }
    __syncthreads();

#pragma unroll
    for (int j = 0; j < 4; j++) {
        const int li = 24 + nl0 + j;
        const float s_i = sT[li];
        float el = (lane < 25) ? lrelu(sT[li - lane] - s_i) : -1e30f;
        const float m = warpMaxAll(el);
        const float ex = (lane < 25) ? __expf(el - m) : 0.f;
        const float rd = 1.f / warpSumAll(ex);
        if (lane < 25) wS[lane][nl0 + j] = ex * rd;
    }
    __syncwarp();

    float2 A[4];
#pragma unroll
    for (int j = 0; j < 4; j++) A[j] = make_float2(0.f, 0.f);

#pragma unroll
    for (int tt = 0; tt < 25; tt++) {
        const float4 wv = *(const float4*)&wS[tt][nl0];
#pragma unroll
        for (int j = 0; j < 4; j++) {
            const float2 zv = ((float2*)zT[24 + nl0 + j - tt])[lane];
            const float g = ((const float*)&wv)[j];
            A[j].x = fmaf(g, zv.x, A[j].x);
            A[j].y = fmaf(g, zv.y, A[j].y);
        }
    }

#pragma unroll
    for (int j = 0; j < 4; j++) {
        const int li = 24 + nl0 + j;
        const int node = nodeBase + nl0 + j;
        const float2 zvi = ((float2*)zT[li])[lane];
        float2 o;
        o.x = A[j].x - zvi.x;
        o.y = A[j].y - zvi.y;
        ((float2*)(g_u + node * 64))[lane] = o;
    }
}

// ---------------- launch ----------------
extern "C" void kernel_launch(void* const* d_in, const int* in_sizes, int n_in,
                              void* d_out, int out_size) {
    const float* h        = (const float*)d_in[0];
    const float* fc_enc   = (const float*)d_in[1];
    const float* diff_enc = (const float*)d_in[2];
    const float* att_enc  = (const float*)d_in[3];
    const float* fc_dec   = (const float*)d_in[4];
    const float* diff_dec = (const float*)d_in[5];
    const float* att_dec  = (const float*)d_in[6];
    const float* att_comb = (const float*)d_in[7];
    float* out = (float*)d_out;

    void *p;
    cudaGetSymbolAddress(&p, g_z1);  float* z1  = (float*)p;
    cudaGetSymbolAddress(&p, g_hd1); float* hd1 = (float*)p;

    gemm_enc<<<(NN + 63) / 64, 256>>>(h, fc_enc, diff_enc, z1, hd1);
    enc_agg<<<NN / 32, 256>>>(att_enc, att_comb);
    dec_agg<<<NN / 32, 256>>>(diff_dec, att_dec);
    gemm_dec<<<(NN + 63) / 64, 256>>>(fc_dec, diff_dec, out);
}